// round 14
// baseline (speedup 1.0000x reference)
#include <cuda_runtime.h>
#include <cstdint>
#include <mma.h>

using namespace nvcuda;

#define DMODEL 1024
#define NH     16
#define DH     64
#define BATCH  4
#define SEQ    1024

// Scratch (static device globals)
__device__ float g_q   [(size_t)BATCH*SEQ*DMODEL];  // [b, i, h*64+d] (tf32)
__device__ float g_k   [(size_t)BATCH*SEQ*DH];      // [b, j, d]      (tf32)
__device__ float g_v   [(size_t)BATCH*SEQ*DH];      // [b, j, d]      (tf32)
__device__ float g_p   [(size_t)64*SEQ*SEQ];        // [b][i][h][j]   (tf32)
__device__ float g_l   [(size_t)BATCH*SEQ*NH];      // row sums
__device__ float g_ctx [(size_t)BATCH*SEQ*DMODEL];  // [b, i, h*64+d] (tf32)
__device__ float g_xr  [(size_t)BATCH*SEQ*DMODEL];  // tf32-rounded x
__device__ float g_wqr [(size_t)DMODEL*DMODEL];     // tf32-rounded Wq
__device__ float g_wor [(size_t)DMODEL*DMODEL];     // tf32-rounded Wo
__device__ float g_wkvr[(size_t)2*DH*DMODEL];       // tf32-rounded [Wk; Wv]

// ---------------------------------------------------------------------------
__device__ __forceinline__ void cp16(void* dst, const void* src) {
    unsigned d = (unsigned)__cvta_generic_to_shared(dst);
    asm volatile("cp.async.cg.shared.global [%0], [%1], 16;" :: "r"(d), "l"(src));
}
__device__ __forceinline__ void cp_commit() { asm volatile("cp.async.commit_group;"); }
template<int N> __device__ __forceinline__ void cp_wait() {
    asm volatile("cp.async.wait_group %0;" :: "n"(N));
}
template<class F> __device__ __forceinline__ void to_tf32(F& f) {
    #pragma unroll
    for (int t = 0; t < f.num_elements; ++t)
        f.x[t] = wmma::__float_to_tf32(f.x[t]);
}

// ---------------------------------------------------------------------------
// Elementwise tf32 rounding, float4-vectorized
// ---------------------------------------------------------------------------
__global__ void round_kernel(const float4* __restrict__ in,
                             float4* __restrict__ out, int n4)
{
    int idx = blockIdx.x * 256 + threadIdx.x;
    if (idx < n4) {
        float4 v = in[idx];
        v.x = wmma::__float_to_tf32(v.x);
        v.y = wmma::__float_to_tf32(v.y);
        v.z = wmma::__float_to_tf32(v.z);
        v.w = wmma::__float_to_tf32(v.w);
        out[idx] = v;
    }
}

// ===========================================================================
// c2cp (warp-autonomous): P[b,i,h,j] = exp(q·(k+rel)/8).
// Each warp owns (batch wb, j-half wn) with PRIVATE smem tiles.  It stages
// its own Q + K via its own cp.async group, folds rel from registers,
// does 16 MMAs, writes its 16x32 P block + rowsum atomics.  No __syncthreads.
// ===========================================================================
struct C2PSmem {
    float Q [8][16][68];   // per-warp Q  (reused as P staging after MMA)
    float KR[8][32][68];   // per-warp K+rel
};
#define C2P_SMEM ((int)sizeof(C2PSmem))

__global__ void __launch_bounds__(256, 2)
c2cp_kernel(const float* __restrict__ rel)
{
    extern __shared__ float smraw[];
    C2PSmem* sm = reinterpret_cast<C2PSmem*>(smraw);

    const int tid  = threadIdx.x;
    const int warp = tid >> 5;
    const int lane = tid & 31;
    const int wb   = warp >> 1;          // batch 0..3
    const int wn   = warp & 1;           // j half
    const int i    = blockIdx.x;
    const int j0w  = blockIdx.y * 64 + wn * 32;

    float (*Qw)[68]  = sm->Q[warp];
    float (*KRw)[68] = sm->KR[warp];

    // ---- stage this warp's Q (16 rows x 64) and K (32 rows x 64)
    #pragma unroll
    for (int l = 0; l < 8; ++l) {        // Q: 256 float4 / 32 lanes
        int idx = lane + l*32;
        int r   = idx >> 4;              // h = 0..15
        int c4  = (idx & 15) * 4;
        cp16(&Qw[r][c4], g_q + ((size_t)(wb*SEQ + i))*DMODEL + r*DH + c4);
    }
    #pragma unroll
    for (int l = 0; l < 16; ++l) {       // K: 512 float4 / 32 lanes
        int idx = lane + l*32;
        int j   = idx >> 4;              // 0..31
        int c4  = (idx & 15) * 4;
        cp16(&KRw[j][c4], g_k + ((size_t)(wb*SEQ + j0w + j))*DH + c4);
    }
    cp_commit();

    // rel loads overlap the cp.async flight (same (j,c4) mapping)
    float4 rv[16];
    #pragma unroll
    for (int l = 0; l < 16; ++l) {
        int idx = lane + l*32;
        int j   = idx >> 4;
        int c4  = (idx & 15) * 4;
        rv[l] = *reinterpret_cast<const float4*>(
            rel + ((size_t)i*SEQ + j0w + j)*DH + c4);
    }
    cp_wait<0>();
    __syncwarp();

    // ---- fold rel into K, round to tf32 (warp-private region)
    #pragma unroll
    for (int l = 0; l < 16; ++l) {
        int idx = lane + l*32;
        int j   = idx >> 4;
        int c4  = (idx & 15) * 4;
        float4 kr = *reinterpret_cast<float4*>(&KRw[j][c4]);
        kr.x = wmma::__float_to_tf32(kr.x + rv[l].x);
        kr.y = wmma::__float_to_tf32(kr.y + rv[l].y);
        kr.z = wmma::__float_to_tf32(kr.z + rv[l].z);
        kr.w = wmma::__float_to_tf32(kr.w + rv[l].w);
        *reinterpret_cast<float4*>(&KRw[j][c4]) = kr;
    }
    __syncwarp();

    // ---- S = Q·(K+R)^T  (16 x 32), raw fragment loads
    wmma::fragment<wmma::accumulator, 16, 16, 8, float> sf[2];
    wmma::fill_fragment(sf[0], 0.0f);
    wmma::fill_fragment(sf[1], 0.0f);
    #pragma unroll
    for (int kf = 0; kf < 8; ++kf) {
        wmma::fragment<wmma::matrix_a, 16, 16, 8, wmma::precision::tf32, wmma::row_major> af;
        wmma::load_matrix_sync(af, &Qw[0][kf*8], 68);
        #pragma unroll
        for (int ni = 0; ni < 2; ++ni) {
            wmma::fragment<wmma::matrix_b, 16, 16, 8, wmma::precision::tf32, wmma::col_major> bk;
            wmma::load_matrix_sync(bk, &KRw[ni*16][kf*8], 68);
            wmma::mma_sync(sf[ni], af, bk, sf[ni]);
        }
    }
    // P = exp(S/8), rounded once (av consumes raw)
    #pragma unroll
    for (int ni = 0; ni < 2; ++ni)
        #pragma unroll
        for (int t = 0; t < sf[ni].num_elements; ++t)
            sf[ni].x[t] = wmma::__float_to_tf32(__expf(sf[ni].x[t] * 0.125f));

    // ---- stage P into this warp's Q tile (no longer needed)
    __syncwarp();
    wmma::store_matrix_sync(&Qw[0][0],  sf[0], 68, wmma::mem_row_major);
    wmma::store_matrix_sync(&Qw[0][16], sf[1], 68, wmma::mem_row_major);
    __syncwarp();

    // ---- writeout + rowsum atomics: 2 lanes per row, 16 cols each
    {
        int r    = lane >> 1;            // 0..15 (h)
        int half = lane & 1;
        size_t grow = ((size_t)(wb*SEQ + i))*16 + r;
        float* dst = g_p + grow*SEQ + j0w + half*16;
        float s = 0.0f;
        #pragma unroll
        for (int c = 0; c < 4; ++c) {
            float4 v = *reinterpret_cast<float4*>(&Qw[r][half*16 + c*4]);
            s += v.x + v.y + v.z + v.w;
            *reinterpret_cast<float4*>(dst + c*4) = v;
        }
        s += __shfl_xor_sync(0xffffffffu, s, 1);
        if (half == 0) atomicAdd(&g_l[grow], s);
    }
}

// ===========================================================================
// AV: ctx[b,(i,h),d] = round_tf32((P_b · V_b) / l).  cp.async double-buffered.
// P and V pre-rounded tf32 — zero cvts in loop.
// ===========================================================================
struct AvSmem { float A[2][128][36]; float B[2][32][68]; };
#define AV_SMEM ((int)sizeof(AvSmem))

__global__ void __launch_bounds__(256, 2)
av_kernel()
{
    extern __shared__ float smraw[];
    AvSmem* sm = reinterpret_cast<AvSmem*>(smraw);

    const int tid  = threadIdx.x;
    const int warp = tid >> 5;
    const int wm   = warp >> 1;
    const int wn   = warp & 1;
    const int b    = blockIdx.y;
    const size_t m0 = (size_t)blockIdx.x * 128;

    const float* Pb = g_p + (size_t)b*SEQ*16*SEQ + m0*SEQ;
    const float* Vb = g_v + (size_t)b*SEQ*DH;
    float*       Cb = g_ctx + ((size_t)b*SEQ*16 + m0)*DH;

    auto stage = [&](int buf, int k0) {
        #pragma unroll
        for (int t = 0; t < 4; ++t) {
            int idx = tid + t*256;
            int r   = idx >> 3;
            int c4  = (idx & 7) * 4;
            cp16(&sm->A[buf][r][c4], Pb + (size_t)r*SEQ + k0 + c4);
        }
        #pragma unroll
        for (int t = 0; t < 2; ++t) {
            int idx = tid + t*256;
            int r   = idx >> 4;
            int c4  = (idx & 15) * 4;
            cp16(&sm->B[buf][r][c4], Vb + (size_t)(k0 + r)*DH + c4);
        }
        cp_commit();
    };

    wmma::fragment<wmma::accumulator, 16, 16, 8, float> of[2][2];
    #pragma unroll
    for (int mi = 0; mi < 2; ++mi)
        #pragma unroll
        for (int ni = 0; ni < 2; ++ni) wmma::fill_fragment(of[mi][ni], 0.0f);

    stage(0, 0);
    int cur = 0;
    for (int k0 = 0; k0 < SEQ; k0 += 32) {
        if (k0 + 32 < SEQ) { stage(cur ^ 1, k0 + 32); cp_wait<1>(); }
        else               { cp_wait<0>(); }
        __syncthreads();

        #pragma unroll
        for (int kf = 0; kf < 4; ++kf) {
            wmma::fragment<wmma::matrix_a, 16, 16, 8, wmma::precision::tf32, wmma::row_major> af[2];
            wmma::fragment<wmma::matrix_b, 16, 16, 8, wmma::precision::tf32, wmma::row_major> bf[2];
            #pragma unroll
            for (int mi = 0; mi < 2; ++mi)
                wmma::load_matrix_sync(af[mi], &sm->A[cur][wm*32 + mi*16][kf*8], 36);
            #pragma unroll
            for (int ni = 0; ni < 2; ++ni)
                wmma::load_matrix_sync(bf[ni], &sm->B[cur][kf*8][wn*32 + ni*16], 68);
            #pragma unroll
            for (int mi = 0; mi < 2; ++mi)
                #pragma unroll
                for (int ni = 0; ni < 2; ++ni)
                    wmma::mma_sync(of[mi][ni], af[mi], bf[ni], of[mi][ni]);
        }
        __syncthreads();
        cur ^= 1;
    }

    float (*Cs)[68] = reinterpret_cast<float (*)[68]>(&sm->A[0][0][0]);
    #pragma unroll
    for (int mi = 0; mi < 2; ++mi)
        #pragma unroll
        for (int ni = 0; ni < 2; ++ni)
            wmma::store_matrix_sync(&Cs[wm*32 + mi*16][wn*32 + ni*16],
                                    of[mi][ni], 68, wmma::mem_row_major);
    __syncthreads();

    {
        int r    = tid >> 1;
        int half = tid & 1;
        float inv = 1.0f / g_l[(size_t)b*SEQ*16 + m0 + r];
        #pragma unroll
        for (int c = 0; c < 8; ++c) {
            float4 v = *reinterpret_cast<float4*>(&Cs[r][half*32 + c*4]);
            v.x = wmma::__float_to_tf32(v.x * inv);
            v.y = wmma::__float_to_tf32(v.y * inv);
            v.z = wmma::__float_to_tf32(v.z * inv);
            v.w = wmma::__float_to_tf32(v.w * inv);
            *reinterpret_cast<float4*>(Cb + (size_t)r*DH + half*32 + c*4) = v;
        }
    }
}

// ===========================================================================
// 128x128 NT GEMM (C = A·B^T) on PRE-ROUNDED inputs — no in-loop cvts.
// round_out=1 rounds C to tf32 at store.
// ===========================================================================
struct ProjSmem { float A[2][128][36]; float B[2][128][36]; };
#define PROJ_SMEM ((int)sizeof(ProjSmem))

__global__ void __launch_bounds__(256, 2)
gemm_nt_128p(const float* __restrict__ A, int lda,
             const float* __restrict__ B, int ldb,
             float* __restrict__ C, int ldc, int K, int round_out)
{
    extern __shared__ float smraw[];
    ProjSmem* sm = reinterpret_cast<ProjSmem*>(smraw);

    const int tid  = threadIdx.x;
    const int warp = tid >> 5;
    const int wm   = warp >> 1;
    const int wn   = warp & 1;

    A += (size_t)blockIdx.x * 128 * lda;
    B += (size_t)blockIdx.y * 128 * ldb;
    C += (size_t)blockIdx.x * 128 * ldc + (size_t)blockIdx.y * 128;

    auto stage = [&](int buf, int k0) {
        #pragma unroll
        for (int t = 0; t < 4; ++t) {
            int idx = tid + t*256;
            int r   = idx >> 3;
            int c4  = (idx & 7) * 4;
            cp16(&sm->A[buf][r][c4], A + (size_t)r*lda + k0 + c4);
            cp16(&sm->B[buf][r][c4], B + (size_t)r*ldb + k0 + c4);
        }
        cp_commit();
    };

    wmma::fragment<wmma::accumulator, 16, 16, 8, float> cf[2][4];
    #pragma unroll
    for (int mi = 0; mi < 2; ++mi)
        #pragma unroll
        for (int ni = 0; ni < 4; ++ni) wmma::fill_fragment(cf[mi][ni], 0.0f);

    stage(0, 0);
    int cur = 0;
    for (int k0 = 0; k0 < K; k0 += 32) {
        if (k0 + 32 < K) { stage(cur ^ 1, k0 + 32); cp_wait<1>(); }
        else             { cp_wait<0>(); }
        __syncthreads();

        #pragma unroll
        for (int kf = 0; kf < 4; ++kf) {
            wmma::fragment<wmma::matrix_a, 16, 16, 8, wmma::precision::tf32, wmma::row_major> af[2];
            wmma::fragment<wmma::matrix_b, 16, 16, 8, wmma::precision::tf32, wmma::col_major> bf[4];
            #pragma unroll
            for (int mi = 0; mi < 2; ++mi)
                wmma::load_matrix_sync(af[mi], &sm->A[cur][wm*32 + mi*16][kf*8], 36);
            #pragma unroll
            for (int ni = 0; ni < 4; ++ni)
                wmma::load_matrix_sync(bf[ni], &sm->B[cur][wn*64 + ni*16][kf*8], 36);
            #pragma unroll
            for (int mi = 0; mi < 2; ++mi)
                #pragma unroll
                for (int ni = 0; ni < 4; ++ni)
                    wmma::mma_sync(cf[mi][ni], af[mi], bf[ni], cf[mi][ni]);
        }
        __syncthreads();
        cur ^= 1;
    }

    if (round_out) {
        #pragma unroll
        for (int mi = 0; mi < 2; ++mi)
            #pragma unroll
            for (int ni = 0; ni < 4; ++ni) to_tf32(cf[mi][ni]);
    }
    #pragma unroll
    for (int mi = 0; mi < 2; ++mi)
        #pragma unroll
        for (int ni = 0; ni < 4; ++ni)
            wmma::store_matrix_sync(
                C + (size_t)(wm*32 + mi*16)*ldc + (wn*64 + ni*16),
                cf[mi][ni], ldc, wmma::mem_row_major);
}

// ===========================================================================
// Combined K/V projection on pre-rounded inputs.  B = g_wkvr rows 0..127.
// Outputs tf32-rounded to g_k / g_v.
// ===========================================================================
__global__ void __launch_bounds__(256, 2)
kv_proj_kernel()
{
    extern __shared__ float smraw[];
    ProjSmem* sm = reinterpret_cast<ProjSmem*>(smraw);

    const int tid  = threadIdx.x;
    const int warp = tid >> 5;
    const int wm   = warp >> 1;
    const int wn   = warp & 1;       // 0 -> K, 1 -> V

    const float* Ax = g_xr + (size_t)blockIdx.x * 128 * DMODEL;

    auto stage = [&](int buf, int k0) {
        #pragma unroll
        for (int t = 0; t < 4; ++t) {
            int idx = tid + t*256;
            int r   = idx >> 3;
            int c4  = (idx & 7) * 4;
            cp16(&sm->A[buf][r][c4], Ax + (size_t)r*DMODEL + k0 + c4);
            cp16(&sm->B[buf][r][c4], g_wkvr + (size_t)r*DMODEL + k0 + c4);
        }
        cp_commit();
    };

    wmma::fragment<wmma::accumulator, 16, 16, 8, float> cf[2][4];
    #pragma unroll
    for (int mi = 0; mi < 2; ++mi)
        #pragma unroll
        for (int ni = 0; ni < 4; ++ni) wmma::fill_fragment(cf[mi][ni], 0.0f);

    stage(0, 0);
    int cur = 0;
    for (int k0 = 0; k0 < DMODEL; k0 += 32) {
        if (k0 + 32 < DMODEL) { stage(cur ^ 1, k0 + 32); cp_wait<1>(); }
        else                  { cp_wait<0>(); }
        __syncthreads();

        #pragma unroll
        for (int kf = 0; kf < 4; ++kf) {
            wmma::fragment<wmma::matrix_a, 16, 16, 8, wmma::precision::tf32, wmma::row_major> af[2];
            wmma::fragment<wmma::matrix_b, 16, 16, 8, wmma::precision::tf32, wmma::col_major> bf[4];
            #pragma unroll
            for (int mi = 0; mi < 2; ++mi)
                wmma::load_matrix_sync(af[mi], &sm->A[cur][wm*32 + mi*16][kf*8], 36);
            #pragma unroll
            for (int ni = 0; ni < 4; ++ni)
                wmma::load_matrix_sync(bf[ni], &sm->B[cur][wn*64 + ni*16][kf*8], 36);
            #pragma unroll
            for (int mi = 0; mi < 2; ++mi)
                #pragma unroll
                for (int ni = 0; ni < 4; ++ni)
                    wmma::mma_sync(cf[mi][ni], af[mi], bf[ni], cf[mi][ni]);
        }
        __syncthreads();
        cur ^= 1;
    }

    #pragma unroll
    for (int mi = 0; mi < 2; ++mi)
        #pragma unroll
        for (int ni = 0; ni < 4; ++ni) to_tf32(cf[mi][ni]);

    float* Ct = (wn == 0) ? g_k : g_v;
    Ct += ((size_t)blockIdx.x * 128 + wm*32) * DH;
    #pragma unroll
    for (int mi = 0; mi < 2; ++mi)
        #pragma unroll
        for (int ni = 0; ni < 4; ++ni)
            wmma::store_matrix_sync(
                Ct + (size_t)(mi*16)*DH + ni*16,
                cf[mi][ni], DH, wmma::mem_row_major);
}

// ---------------------------------------------------------------------------
__global__ void bias_add(float* __restrict__ out, const float* __restrict__ bo)
{
    size_t idx = (size_t)blockIdx.x * 256 + threadIdx.x;
    out[idx] += bo[idx & (DMODEL - 1)];
}

// ---------------------------------------------------------------------------
extern "C" void kernel_launch(void* const* d_in, const int* in_sizes, int n_in,
                              void* d_out, int out_size)
{
    const float* x   = (const float*)d_in[0];
    const float* rel = (const float*)d_in[1];
    const float* Wq  = (const float*)d_in[2];
    const float* Wk  = (const float*)d_in[3];
    const float* Wv  = (const float*)d_in[4];
    const float* Wo  = (const float*)d_in[5];
    const float* bo  = (const float*)d_in[6];
    float* out = (float*)d_out;

    float *q, *l, *ctx, *xr, *wqr, *wor, *wkvr;
    cudaGetSymbolAddress((void**)&q,    g_q);
    cudaGetSymbolAddress((void**)&l,    g_l);
    cudaGetSymbolAddress((void**)&ctx,  g_ctx);
    cudaGetSymbolAddress((void**)&xr,   g_xr);
    cudaGetSymbolAddress((void**)&wqr,  g_wqr);
    cudaGetSymbolAddress((void**)&wor,  g_wor);
    cudaGetSymbolAddress((void**)&wkvr, g_wkvr);

    cudaFuncSetAttribute(gemm_nt_128p,   cudaFuncAttributeMaxDynamicSharedMemorySize, PROJ_SMEM);
    cudaFuncSetAttribute(kv_proj_kernel, cudaFuncAttributeMaxDynamicSharedMemorySize, PROJ_SMEM);
    cudaFuncSetAttribute(c2cp_kernel,    cudaFuncAttributeMaxDynamicSharedMemorySize, C2P_SMEM);
    cudaFuncSetAttribute(av_kernel,      cudaFuncAttributeMaxDynamicSharedMemorySize, AV_SMEM);

    // Pre-round inputs to tf32 (producer-side; removes all in-loop cvts)
    round_kernel<<<(BATCH*SEQ*DMODEL/4 + 255)/256, 256>>>((const float4*)x,  (float4*)xr,   BATCH*SEQ*DMODEL/4);
    round_kernel<<<(DMODEL*DMODEL/4    + 255)/256, 256>>>((const float4*)Wq, (float4*)wqr,  DMODEL*DMODEL/4);
    round_kernel<<<(DMODEL*DMODEL/4    + 255)/256, 256>>>((const float4*)Wo, (float4*)wor,  DMODEL*DMODEL/4);
    round_kernel<<<(DH*DMODEL/4        + 255)/256, 256>>>((const float4*)Wk, (float4*)wkvr, DH*DMODEL/4);
    round_kernel<<<(DH*DMODEL/4        + 255)/256, 256>>>((const float4*)Wv, (float4*)(wkvr + (size_t)DH*DMODEL), DH*DMODEL/4);

    // Projections: y = x @ W^T  (outputs tf32-rounded at source)
    gemm_nt_128p<<<dim3(32, 8), 256, PROJ_SMEM>>>(xr, DMODEL, wqr, DMODEL, q, DMODEL, DMODEL, 1);
    kv_proj_kernel<<<32, 256, PROJ_SMEM>>>();

    // Zero row-sum accumulators
    cudaMemsetAsync(l, 0, (size_t)BATCH*SEQ*NH*sizeof(float));

    // P = exp(q·(k+rel)/8), warp-autonomous, row sums via atomics
    c2cp_kernel<<<dim3(SEQ, SEQ/64), 256, C2P_SMEM>>>(rel);

    // ctx = round_tf32((P · V) / l)
    av_kernel<<<dim3(128, BATCH), 256, AV_SMEM>>>();

    // out = ctx @ Wo^T + bo
    gemm_nt_128p<<<dim3(32, 8), 256, PROJ_SMEM>>>(ctx, DMODEL, wor, DMODEL, out, DMODEL, DMODEL, 0);
    bias_add<<<16384, 256>>>(out, bo);
}

// round 15
// speedup vs baseline: 1.1242x; 1.1242x over previous
#include <cuda_runtime.h>
#include <cstdint>
#include <mma.h>

using namespace nvcuda;

#define DMODEL 1024
#define NH     16
#define DH     64
#define BATCH  4
#define SEQ    1024
#define NCC    32            // c2cp j-chunks of 32

// Scratch (static device globals)
__device__ float g_q   [(size_t)BATCH*SEQ*DMODEL];  // [b, i, h*64+d] (tf32)
__device__ float g_k   [(size_t)BATCH*SEQ*DH];      // [b, j, d]      (tf32)
__device__ float g_v   [(size_t)BATCH*SEQ*DH];      // [b, j, d]      (tf32)
__device__ float g_p   [(size_t)64*SEQ*SEQ];        // [b][i][h][j]   (tf32)
__device__ float g_l   [(size_t)BATCH*SEQ*NH];      // row sums
__device__ float g_ctx [(size_t)BATCH*SEQ*DMODEL];  // [b, i, h*64+d]

// ---------------------------------------------------------------------------
__device__ __forceinline__ void cp16(void* dst, const void* src) {
    unsigned d = (unsigned)__cvta_generic_to_shared(dst);
    asm volatile("cp.async.cg.shared.global [%0], [%1], 16;" :: "r"(d), "l"(src));
}
__device__ __forceinline__ void cp_commit() { asm volatile("cp.async.commit_group;"); }
template<int N> __device__ __forceinline__ void cp_wait() {
    asm volatile("cp.async.wait_group %0;" :: "n"(N));
}
template<class F> __device__ __forceinline__ void to_tf32(F& f) {
    #pragma unroll
    for (int t = 0; t < f.num_elements; ++t)
        f.x[t] = wmma::__float_to_tf32(f.x[t]);
}

// ===========================================================================
// c2cp v2: CTA per i, pipelined loop over 32 j-chunks of 32.
//   P[b,i,h,j] = exp(q·(k+rel)/8)  with the fold  q·k + q·rel = q·(k+rel).
// Q resident in smem; K double-buffered cp.async; rel prefetched to regs and
// folded cooperatively.  CTA owns all of row i -> row sums in smem, one store.
// ===========================================================================
struct C2PSmem {
    float Qs[64][68];            // rows (b,h), cols d          (17.4 KB)
    float KR[2][4][32][68];      // [buf][b][j][d] = k (+rel)   (69.6 KB)
    float Ps[8][16][16];         // per-warp P staging          ( 8.2 KB)
    float lsum[8][16];           // per-warp row-sum partials
};
#define C2P_SMEM ((int)sizeof(C2PSmem))

__global__ void __launch_bounds__(256, 2)
c2cp_kernel(const float* __restrict__ rel)
{
    extern __shared__ float smraw[];
    C2PSmem* sm = reinterpret_cast<C2PSmem*>(smraw);

    const int tid  = threadIdx.x;
    const int warp = tid >> 5;
    const int lane = tid & 31;
    const int wb   = warp >> 1;          // batch 0..3
    const int wn   = warp & 1;           // j half of chunk
    const int i    = blockIdx.x;

    auto stageK = [&](int s, int j0) {
        #pragma unroll
        for (int t = 0; t < 8; ++t) {            // 2048 float4
            int idx = tid + t*256;
            int b   = idx >> 9;
            int j   = (idx >> 4) & 31;
            int c4  = (idx & 15) * 4;
            cp16(&sm->KR[s][b][j][c4], g_k + ((size_t)(b*SEQ + j0 + j))*DH + c4);
        }
        cp_commit();
    };
    auto relload = [&](int c, float4* rv) {
        #pragma unroll
        for (int t = 0; t < 2; ++t) {            // 512 float4
            int idx = tid + t*256;
            int j   = idx >> 4;
            int c4  = (idx & 15) * 4;
            rv[t] = *reinterpret_cast<const float4*>(
                rel + ((size_t)i*SEQ + c*32 + j)*DH + c4);
        }
    };

    // ---- prologue: Q (group 0 together with K chunk 0)
    #pragma unroll
    for (int t = 0; t < 4; ++t) {                // 1024 float4
        int idx = tid + t*256;
        int r   = idx >> 4;
        int c4  = (idx & 15) * 4;
        cp16(&sm->Qs[r][c4],
             g_q + ((size_t)((r >> 4)*SEQ + i))*DMODEL + (r & 15)*DH + c4);
    }
    stageK(0, 0);
    if (tid < 128) (&sm->lsum[0][0])[tid] = 0.0f;
    float4 rv[2];
    relload(0, rv);

    for (int c = 0; c < NCC; ++c) {
        const int pb = c & 1;
        if (c + 1 < NCC) stageK(pb ^ 1, (c + 1)*32); else cp_commit();
        cp_wait<1>();
        __syncthreads();                 // K(c) landed (incl. Q on c==0)

        // ---- cooperative fold: KR[pb][b][j][d] = round(k + rel[i][j][d])
        #pragma unroll
        for (int t = 0; t < 2; ++t) {
            int idx = tid + t*256;
            int j   = idx >> 4;
            int c4  = (idx & 15) * 4;
            #pragma unroll
            for (int b = 0; b < 4; ++b) {
                float4 kr = *reinterpret_cast<float4*>(&sm->KR[pb][b][j][c4]);
                kr.x = wmma::__float_to_tf32(kr.x + rv[t].x);
                kr.y = wmma::__float_to_tf32(kr.y + rv[t].y);
                kr.z = wmma::__float_to_tf32(kr.z + rv[t].z);
                kr.w = wmma::__float_to_tf32(kr.w + rv[t].w);
                *reinterpret_cast<float4*>(&sm->KR[pb][b][j][c4]) = kr;
            }
        }
        __syncthreads();                 // fold visible

        float4 rvn[2];
        if (c + 1 < NCC) relload(c + 1, rvn);   // LDGs overlap MMAs

        // ---- S = Q·(K+R)^T  (warp: 16 h-rows x 16 j), raw fragment loads
        wmma::fragment<wmma::accumulator, 16, 16, 8, float> sf;
        wmma::fill_fragment(sf, 0.0f);
        #pragma unroll
        for (int kf = 0; kf < 8; ++kf) {
            wmma::fragment<wmma::matrix_a, 16, 16, 8, wmma::precision::tf32, wmma::row_major> af;
            wmma::fragment<wmma::matrix_b, 16, 16, 8, wmma::precision::tf32, wmma::col_major> bk;
            wmma::load_matrix_sync(af, &sm->Qs[wb*16][kf*8], 68);
            wmma::load_matrix_sync(bk, &sm->KR[pb][wb][wn*16][kf*8], 68);
            wmma::mma_sync(sf, af, bk, sf);
        }
        #pragma unroll
        for (int t = 0; t < sf.num_elements; ++t)
            sf.x[t] = wmma::__float_to_tf32(__expf(sf.x[t] * 0.125f));

        wmma::store_matrix_sync(&sm->Ps[warp][0][0], sf, 16, wmma::mem_row_major);
        __syncwarp();

        // ---- writeout + row-sum accumulation (warp-local)
        {
            int r    = lane >> 1;                // h = 0..15
            int half = lane & 1;
            size_t grow = ((size_t)(wb*SEQ + i))*16 + r;
            float* dst = g_p + grow*SEQ + c*32 + wn*16 + half*8;
            float s = 0.0f;
            #pragma unroll
            for (int q = 0; q < 2; ++q) {
                float4 v = *reinterpret_cast<float4*>(&sm->Ps[warp][r][half*8 + q*4]);
                s += v.x + v.y + v.z + v.w;
                *reinterpret_cast<float4*>(dst + q*4) = v;
            }
            s += __shfl_xor_sync(0xffffffffu, s, 1);
            if (half == 0) sm->lsum[warp][r] += s;
        }
        rv[0] = rvn[0]; rv[1] = rvn[1];
        __syncthreads();                 // all reads of KR[pb] done before restage
    }

    // ---- row sums: CTA owns row i entirely -> direct store, no atomics
    if (tid < 64) {
        int b = tid >> 4, h = tid & 15;
        g_l[((size_t)(b*SEQ + i))*16 + h] =
            sm->lsum[b*2 + 0][h] + sm->lsum[b*2 + 1][h];
    }
}

// ===========================================================================
// AV: ctx[b,(i,h),d] = (P_b · V_b) / l.   3-stage cp.async pipeline.
// P and V pre-rounded tf32 — zero cvts in loop.
// ===========================================================================
struct AvSmem { float A[3][128][36]; float B[3][32][68]; };
#define AV_SMEM ((int)sizeof(AvSmem))

__global__ void __launch_bounds__(256, 2)
av_kernel()
{
    extern __shared__ float smraw[];
    AvSmem* sm = reinterpret_cast<AvSmem*>(smraw);

    const int tid  = threadIdx.x;
    const int warp = tid >> 5;
    const int wm   = warp >> 1;
    const int wn   = warp & 1;
    const int b    = blockIdx.y;
    const size_t m0 = (size_t)blockIdx.x * 128;

    const float* Pb = g_p + (size_t)b*SEQ*16*SEQ + m0*SEQ;
    const float* Vb = g_v + (size_t)b*SEQ*DH;
    float*       Cb = g_ctx + ((size_t)b*SEQ*16 + m0)*DH;

    auto stage = [&](int s, int k0) {
        #pragma unroll
        for (int t = 0; t < 4; ++t) {
            int idx = tid + t*256;
            int r   = idx >> 3;
            int c4  = (idx & 7) * 4;
            cp16(&sm->A[s][r][c4], Pb + (size_t)r*SEQ + k0 + c4);
        }
        #pragma unroll
        for (int t = 0; t < 2; ++t) {
            int idx = tid + t*256;
            int r   = idx >> 4;
            int c4  = (idx & 15) * 4;
            cp16(&sm->B[s][r][c4], Vb + (size_t)(k0 + r)*DH + c4);
        }
        cp_commit();
    };

    wmma::fragment<wmma::accumulator, 16, 16, 8, float> of[2][2];
    #pragma unroll
    for (int mi = 0; mi < 2; ++mi)
        #pragma unroll
        for (int ni = 0; ni < 2; ++ni) wmma::fill_fragment(of[mi][ni], 0.0f);

    stage(0, 0);
    stage(1, 32);
    for (int c = 0; c < 32; ++c) {
        const int buf = c % 3;
        if (c + 2 < 32) stage((c + 2) % 3, (c + 2)*32); else cp_commit();
        cp_wait<2>();
        __syncthreads();

        #pragma unroll
        for (int kf = 0; kf < 4; ++kf) {
            wmma::fragment<wmma::matrix_a, 16, 16, 8, wmma::precision::tf32, wmma::row_major> af[2];
            wmma::fragment<wmma::matrix_b, 16, 16, 8, wmma::precision::tf32, wmma::row_major> bf[2];
            #pragma unroll
            for (int mi = 0; mi < 2; ++mi)
                wmma::load_matrix_sync(af[mi], &sm->A[buf][wm*32 + mi*16][kf*8], 36);
            #pragma unroll
            for (int ni = 0; ni < 2; ++ni)
                wmma::load_matrix_sync(bf[ni], &sm->B[buf][kf*8][wn*32 + ni*16], 68);
            #pragma unroll
            for (int mi = 0; mi < 2; ++mi)
                #pragma unroll
                for (int ni = 0; ni < 2; ++ni)
                    wmma::mma_sync(of[mi][ni], af[mi], bf[ni], of[mi][ni]);
        }
        __syncthreads();
    }

    float (*Cs)[68] = reinterpret_cast<float (*)[68]>(&sm->A[0][0][0]);
    #pragma unroll
    for (int mi = 0; mi < 2; ++mi)
        #pragma unroll
        for (int ni = 0; ni < 2; ++ni)
            wmma::store_matrix_sync(&Cs[wm*32 + mi*16][wn*32 + ni*16],
                                    of[mi][ni], 68, wmma::mem_row_major);
    __syncthreads();

    {
        int r    = tid >> 1;
        int half = tid & 1;
        float inv = 1.0f / g_l[(size_t)b*SEQ*16 + m0 + r];
        #pragma unroll
        for (int cc = 0; cc < 8; ++cc) {
            float4 v = *reinterpret_cast<float4*>(&Cs[r][half*32 + cc*4]);
            v.x *= inv; v.y *= inv; v.z *= inv; v.w *= inv;
            *reinterpret_cast<float4*>(Cb + (size_t)r*DH + half*32 + cc*4) = v;
        }
    }
}

// ===========================================================================
// QKV projection: one grid.  blockIdx.y < 8 -> Q output columns y*128..;
// blockIdx.y == 8 -> stacked [Wk; Wv] -> g_k / g_v (tf32-rounded).
// 3-stage cp.async, per-fragment tf32 cvts (R13-proven).
// ===========================================================================
struct ProjSmem { float A[3][128][36]; float B[3][128][36]; };
#define PROJ_SMEM ((int)sizeof(ProjSmem))

__global__ void __launch_bounds__(256, 2)
qkv_kernel(const float* __restrict__ x,
           const float* __restrict__ Wq,
           const float* __restrict__ Wk,
           const float* __restrict__ Wv,
           float* __restrict__ q)
{
    extern __shared__ float smraw[];
    ProjSmem* sm = reinterpret_cast<ProjSmem*>(smraw);

    const int tid  = threadIdx.x;
    const int warp = tid >> 5;
    const int wm   = warp >> 1;
    const int wn   = warp & 1;
    const int by   = blockIdx.y;
    const bool kv  = (by == 8);

    const float* Ax = x + (size_t)blockIdx.x * 128 * DMODEL;

    auto stage = [&](int s, int k0) {
        #pragma unroll
        for (int t = 0; t < 4; ++t) {
            int idx = tid + t*256;
            int r   = idx >> 3;
            int c4  = (idx & 7) * 4;
            cp16(&sm->A[s][r][c4], Ax + (size_t)r*DMODEL + k0 + c4);
            const float* src;
            if (kv) src = (r < 64) ? (Wk + (size_t)r*DMODEL)
                                   : (Wv + (size_t)(r - 64)*DMODEL);
            else    src = Wq + (size_t)(by*128 + r)*DMODEL;
            cp16(&sm->B[s][r][c4], src + k0 + c4);
        }
        cp_commit();
    };

    wmma::fragment<wmma::accumulator, 16, 16, 8, float> cf[2][4];
    #pragma unroll
    for (int mi = 0; mi < 2; ++mi)
        #pragma unroll
        for (int ni = 0; ni < 4; ++ni) wmma::fill_fragment(cf[mi][ni], 0.0f);

    stage(0, 0);
    stage(1, 32);
    for (int c = 0; c < 32; ++c) {
        const int buf = c % 3;
        if (c + 2 < 32) stage((c + 2) % 3, (c + 2)*32); else cp_commit();
        cp_wait<2>();
        __syncthreads();

        #pragma unroll
        for (int kf = 0; kf < 4; ++kf) {
            wmma::fragment<wmma::matrix_a, 16, 16, 8, wmma::precision::tf32, wmma::row_major> af[2];
            wmma::fragment<wmma::matrix_b, 16, 16, 8, wmma::precision::tf32, wmma::col_major> bf[4];
            #pragma unroll
            for (int mi = 0; mi < 2; ++mi) {
                wmma::load_matrix_sync(af[mi], &sm->A[buf][wm*32 + mi*16][kf*8], 36);
                to_tf32(af[mi]);
            }
            #pragma unroll
            for (int ni = 0; ni < 4; ++ni) {
                wmma::load_matrix_sync(bf[ni], &sm->B[buf][wn*64 + ni*16][kf*8], 36);
                to_tf32(bf[ni]);
            }
            #pragma unroll
            for (int mi = 0; mi < 2; ++mi)
                #pragma unroll
                for (int ni = 0; ni < 4; ++ni)
                    wmma::mma_sync(cf[mi][ni], af[mi], bf[ni], cf[mi][ni]);
        }
        __syncthreads();
    }

    #pragma unroll
    for (int mi = 0; mi < 2; ++mi)
        #pragma unroll
        for (int ni = 0; ni < 4; ++ni) to_tf32(cf[mi][ni]);   // round outputs

    if (!kv) {
        float* C = q + (size_t)blockIdx.x * 128 * DMODEL + (size_t)by * 128;
        #pragma unroll
        for (int mi = 0; mi < 2; ++mi)
            #pragma unroll
            for (int ni = 0; ni < 4; ++ni)
                wmma::store_matrix_sync(
                    C + (size_t)(wm*32 + mi*16)*DMODEL + (wn*64 + ni*16),
                    cf[mi][ni], DMODEL, wmma::mem_row_major);
    } else {
        float* Ct = (wn == 0) ? g_k : g_v;
        Ct += ((size_t)blockIdx.x * 128 + wm*32) * DH;
        #pragma unroll
        for (int mi = 0; mi < 2; ++mi)
            #pragma unroll
            for (int ni = 0; ni < 4; ++ni)
                wmma::store_matrix_sync(
                    Ct + (size_t)(mi*16)*DH + ni*16,
                    cf[mi][ni], DH, wmma::mem_row_major);
    }
}

// ===========================================================================
// O projection: 128x128 NT GEMM, 3-stage, per-fragment cvts.
// ===========================================================================
__global__ void __launch_bounds__(256, 2)
gemm_nt_128p(const float* __restrict__ A, int lda,
             const float* __restrict__ B, int ldb,
             float* __restrict__ C, int ldc, int K)
{
    extern __shared__ float smraw[];
    ProjSmem* sm = reinterpret_cast<ProjSmem*>(smraw);

    const int tid  = threadIdx.x;
    const int warp = tid >> 5;
    const int wm   = warp >> 1;
    const int wn   = warp & 1;

    A += (size_t)blockIdx.x * 128 * lda;
    B += (size_t)blockIdx.y * 128 * ldb;
    C += (size_t)blockIdx.x * 128 * ldc + (size_t)blockIdx.y * 128;

    auto stage = [&](int s, int k0) {
        #pragma unroll
        for (int t = 0; t < 4; ++t) {
            int idx = tid + t*256;
            int r   = idx >> 3;
            int c4  = (idx & 7) * 4;
            cp16(&sm->A[s][r][c4], A + (size_t)r*lda + k0 + c4);
            cp16(&sm->B[s][r][c4], B + (size_t)r*ldb + k0 + c4);
        }
        cp_commit();
    };

    wmma::fragment<wmma::accumulator, 16, 16, 8, float> cf[2][4];
    #pragma unroll
    for (int mi = 0; mi < 2; ++mi)
        #pragma unroll
        for (int ni = 0; ni < 4; ++ni) wmma::fill_fragment(cf[mi][ni], 0.0f);

    const int nc = K / 32;
    stage(0, 0);
    stage(1, 32);
    for (int c = 0; c < nc; ++c) {
        const int buf = c % 3;
        if (c + 2 < nc) stage((c + 2) % 3, (c + 2)*32); else cp_commit();
        cp_wait<2>();
        __syncthreads();

        #pragma unroll
        for (int kf = 0; kf < 4; ++kf) {
            wmma::fragment<wmma::matrix_a, 16, 16, 8, wmma::precision::tf32, wmma::row_major> af[2];
            wmma::fragment<wmma::matrix_b, 16, 16, 8, wmma::precision::tf32, wmma::col_major> bf[4];
            #pragma unroll
            for (int mi = 0; mi < 2; ++mi) {
                wmma::load_matrix_sync(af[mi], &sm->A[buf][wm*32 + mi*16][kf*8], 36);
                to_tf32(af[mi]);
            }
            #pragma unroll
            for (int ni = 0; ni < 4; ++ni) {
                wmma::load_matrix_sync(bf[ni], &sm->B[buf][wn*64 + ni*16][kf*8], 36);
                to_tf32(bf[ni]);
            }
            #pragma unroll
            for (int mi = 0; mi < 2; ++mi)
                #pragma unroll
                for (int ni = 0; ni < 4; ++ni)
                    wmma::mma_sync(cf[mi][ni], af[mi], bf[ni], cf[mi][ni]);
        }
        __syncthreads();
    }

    #pragma unroll
    for (int mi = 0; mi < 2; ++mi)
        #pragma unroll
        for (int ni = 0; ni < 4; ++ni)
            wmma::store_matrix_sync(
                C + (size_t)(wm*32 + mi*16)*ldc + (wn*64 + ni*16),
                cf[mi][ni], ldc, wmma::mem_row_major);
}

// ---------------------------------------------------------------------------
__global__ void bias_add(float* __restrict__ out, const float* __restrict__ bo)
{
    size_t idx = (size_t)blockIdx.x * 256 + threadIdx.x;
    out[idx] += bo[idx & (DMODEL - 1)];
}

// ---------------------------------------------------------------------------
extern "C" void kernel_launch(void* const* d_in, const int* in_sizes, int n_in,
                              void* d_out, int out_size)
{
    const float* x   = (const float*)d_in[0];
    const float* rel = (const float*)d_in[1];
    const float* Wq  = (const float*)d_in[2];
    const float* Wk  = (const float*)d_in[3];
    const float* Wv  = (const float*)d_in[4];
    const float* Wo  = (const float*)d_in[5];
    const float* bo  = (const float*)d_in[6];
    float* out = (float*)d_out;

    float *q, *ctx;
    cudaGetSymbolAddress((void**)&q,   g_q);
    cudaGetSymbolAddress((void**)&ctx, g_ctx);

    cudaFuncSetAttribute(qkv_kernel,   cudaFuncAttributeMaxDynamicSharedMemorySize, PROJ_SMEM);
    cudaFuncSetAttribute(gemm_nt_128p, cudaFuncAttributeMaxDynamicSharedMemorySize, PROJ_SMEM);
    cudaFuncSetAttribute(c2cp_kernel,  cudaFuncAttributeMaxDynamicSharedMemorySize, C2P_SMEM);
    cudaFuncSetAttribute(av_kernel,    cudaFuncAttributeMaxDynamicSharedMemorySize, AV_SMEM);

    // Q + K + V projections in one grid (outputs tf32-rounded)
    qkv_kernel<<<dim3(32, 9), 256, PROJ_SMEM>>>(x, Wq, Wk, Wv, q);

    // P = exp(q·(k+rel)/8); row sums stored directly (no atomics/memset)
    c2cp_kernel<<<SEQ, 256, C2P_SMEM>>>(rel);

    // ctx = (P · V) / l
    av_kernel<<<dim3(128, BATCH), 256, AV_SMEM>>>();

    // out = ctx @ Wo^T + bo
    gemm_nt_128p<<<dim3(32, 8), 256, PROJ_SMEM>>>(ctx, DMODEL, Wo, DMODEL, out, DMODEL, DMODEL);
    bias_add<<<16384, 256>>>(out, bo);
}